// round 11
// baseline (speedup 1.0000x reference)
#include <cuda_runtime.h>
#include <cstdint>

#define NTOK 262144
#define DF 128
#define CC 64
#define TILES 2048
#define GRID 152
#define NTHR 512

// ---- static device scratch (per-CTA partials) ----
__device__ float g_Fpart[GRID * CC * DF];
__device__ int   g_cntpart[GRID * CC];
__device__ float g_f2part[GRID];
__device__ float g_s2part[CC];
__device__ float g_nc2[CC];

// ---- shared memory byte offsets ----
#define SM_A0    0          // float[128*132] tile buffer 0 (67584)
#define SM_A1    67584      // float[128*132] tile buffer 1 (67584)
#define SM_FSUM  135168     // float[64*132]  per-CTA class sums (33792)
#define SM_STAGE 168960     // float[128*66]  staging; ctf alias at init (33792)
#define SM_F2B   202752     // float[2][128]  f2 double buffer (1024)
#define SM_C2    203776     // float[64]
#define SM_LBL   204032     // int[128]
#define SM_CNT   204544     // int[64]
#define SM_CNTT  204800     // int[64]
#define SM_LIST  205056     // u8[64*128] (8192)
#define SM_TOTAL 213248

// named barriers: 1,2 = A-full[par]; 3,4 = A-empty[par]; 5 = producer-only;
//                 6 = stage-full; 7 = stage-empty
#define BAR_SYNC(id, n) asm volatile("bar.sync %0, %1;" :: "r"(id), "r"(n) : "memory")
#define BAR_ARR(id, n)  asm volatile("bar.arrive %0, %1;" :: "r"(id), "r"(n) : "memory")
#define MEMBAR_CTA()    asm volatile("membar.cta;" ::: "memory")

__device__ __forceinline__ float tf32r(float x) {
    unsigned u;
    asm("cvt.rna.tf32.f32 %0, %1;" : "=r"(u) : "f"(x));
    return __uint_as_float(u);
}
__device__ __forceinline__ void mma_tf32(float* d, unsigned a0, unsigned a1,
                                         unsigned a2, unsigned a3,
                                         unsigned b0, unsigned b1) {
    asm volatile(
        "mma.sync.aligned.m16n8k8.row.col.f32.tf32.tf32.f32 "
        "{%0,%1,%2,%3}, {%4,%5,%6,%7}, {%8,%9}, {%0,%1,%2,%3};"
        : "+f"(d[0]), "+f"(d[1]), "+f"(d[2]), "+f"(d[3])
        : "r"(a0), "r"(a1), "r"(a2), "r"(a3), "r"(b0), "r"(b1));
}

// ============================================================
__global__ void __launch_bounds__(NTHR, 1)
k_main(const float* __restrict__ feature, const int* __restrict__ label,
       const float* __restrict__ centers, float* __restrict__ out)
{
    extern __shared__ __align__(16) char sm[];
    float*         F_sm    = (float*)(sm + SM_FSUM);
    float*         stage   = (float*)(sm + SM_STAGE);
    float*         ctf     = (float*)(sm + SM_STAGE);   // init-time alias
    float*         f2b     = (float*)(sm + SM_F2B);     // [2][128]
    float*         c2_sm   = (float*)(sm + SM_C2);
    int*           lbl_sm  = (int*)(sm + SM_LBL);
    int*           cnt_sm  = (int*)(sm + SM_CNT);
    int*           cntt_sm = (int*)(sm + SM_CNTT);
    unsigned char* list_sm = (unsigned char*)(sm + SM_LIST);

    const int tid = threadIdx.x, bid = blockIdx.x;
    const int w = tid >> 5, l = tid & 31;
    const int lq = l >> 2, lr = l & 3;

    // ---- one-time init (all threads) ----
    for (int i = tid; i < CC * 132; i += NTHR) F_sm[i] = 0.f;
    for (int i = tid; i < CC * DF; i += NTHR)
        ctf[(i >> 7) * 132 + (i & 127)] = tf32r(centers[i]);
    if (tid < CC) {
        float s = 0.f;
        for (int k = 0; k < DF; k++) { float c = centers[tid * DF + k]; s += c * c; }
        c2_sm[tid] = s;
        cntt_sm[tid] = 0;
    }
    __syncthreads();

    const int nIters = (TILES - bid + GRID - 1) / GRID;
    double f2acc = 0.0;

    if (w < 8) {
        // ================= CONSUMER: GEMM + epilogue =================
        const int mbase = (w >> 2) * 64;        // 2 m-super-groups of 64 tokens
        const int nbase = (w & 3) * 16;         // 4 n-groups of 16 classes

        unsigned bfr[16][2][2];
        #pragma unroll
        for (int kc = 0; kc < 16; kc++)
            #pragma unroll
            for (int j = 0; j < 2; j++) {
                const float* cp = &ctf[(nbase + j * 8 + lq) * 132 + kc * 8 + lr];
                bfr[kc][j][0] = __float_as_uint(cp[0]);
                bfr[kc][j][1] = __float_as_uint(cp[4]);
            }
        __syncthreads();                        // ctf read; stage free

        for (int i = 0; i < nIters; i++) {
            const int par = i & 1;
            BAR_SYNC(1 + par, NTHR);            // A[par] + f2b[par] ready
            const float* atf = (const float*)(sm + (par ? SM_A1 : SM_A0));
            const float* f2p = f2b + par * 128;

            float acc[4][2][4];
            #pragma unroll
            for (int mi = 0; mi < 4; mi++)
                #pragma unroll
                for (int j = 0; j < 2; j++)
                    #pragma unroll
                    for (int e = 0; e < 4; e++) acc[mi][j][e] = 0.f;

            #pragma unroll
            for (int kc = 0; kc < 16; kc++) {
                #pragma unroll
                for (int mi = 0; mi < 4; mi++) {
                    const float* ap = &atf[(mbase + mi * 16 + lq) * 132 + kc * 8 + lr];
                    unsigned a0 = __float_as_uint(ap[0]);
                    unsigned a2 = __float_as_uint(ap[4]);
                    unsigned a1 = __float_as_uint(ap[8 * 132]);
                    unsigned a3 = __float_as_uint(ap[8 * 132 + 4]);
                    mma_tf32(acc[mi][0], a0, a1, a2, a3, bfr[kc][0][0], bfr[kc][0][1]);
                    mma_tf32(acc[mi][1], a0, a1, a2, a3, bfr[kc][1][0], bfr[kc][1][1]);
                }
            }

            if (i > 0) BAR_SYNC(7, NTHR);       // stage free (store of i-1 done)

            #pragma unroll
            for (int mi = 0; mi < 4; mi++) {
                const int r0 = mbase + mi * 16 + lq;
                const float ft0 = f2p[r0], ft1 = f2p[r0 + 8];
                #pragma unroll
                for (int j = 0; j < 2; j++) {
                    const int n0 = nbase + j * 8 + lr * 2;
                    const float cA = c2_sm[n0], cB = c2_sm[n0 + 1];
                    float2 v0, v1;
                    v0.x = fmaf(-2.f, acc[mi][j][0], ft0 + cA);
                    v0.y = fmaf(-2.f, acc[mi][j][1], ft0 + cB);
                    v1.x = fmaf(-2.f, acc[mi][j][2], ft1 + cA);
                    v1.y = fmaf(-2.f, acc[mi][j][3], ft1 + cB);
                    *(float2*)&stage[r0 * 66 + n0] = v0;
                    *(float2*)&stage[(r0 + 8) * 66 + n0] = v1;
                }
            }
            MEMBAR_CTA();
            BAR_ARR(6, NTHR);                   // stage full
            BAR_ARR(3 + par, NTHR);             // A[par] + f2b[par] free
        }
    } else {
        // ================= PRODUCER: load/f2/lists/phase3/store =================
        const int wp = w - 8;                   // 0..7
        const int wp_tid = tid - 256;           // 0..255
        __syncthreads();                        // match consumer's bfr barrier

        for (int i = 0; i < nIters; i++) {
            const int par = i & 1;
            const int tile = bid + i * GRID;
            const int base = tile * 128;
            float* atf = (float*)(sm + (par ? SM_A1 : SM_A0));
            float* f2p = f2b + par * 128;

            if (i >= 2) BAR_SYNC(3 + par, NTHR);   // buffer free

            // load 16 rows per warp: row = k*8 + wp, warp covers full row
            #pragma unroll
            for (int k = 0; k < 16; k++) {
                const int row = k * 8 + wp;
                float4 f4 = *(const float4*)&feature[(size_t)(base + row) * DF + l * 4];
                float s = f4.x * f4.x + f4.y * f4.y + f4.z * f4.z + f4.w * f4.w;
                #pragma unroll
                for (int o = 16; o; o >>= 1) s += __shfl_xor_sync(0xffffffffu, s, o);
                if (l == 0) f2p[row] = s;
                f4.x = tf32r(f4.x); f4.y = tf32r(f4.y);
                f4.z = tf32r(f4.z); f4.w = tf32r(f4.w);
                *(float4*)&atf[row * 132 + l * 4] = f4;
            }
            if (wp_tid < 128)       lbl_sm[wp_tid] = label[base + wp_tid] & (CC - 1);
            else if (wp_tid < 192)  cnt_sm[wp_tid - 128] = 0;

            BAR_SYNC(5, 256);                   // producer-internal: tile visible
            MEMBAR_CTA();
            BAR_ARR(1 + par, NTHR);             // A[par] full -> consumers go

            if (wp_tid < 128) {
                int c = lbl_sm[wp_tid];
                int pos = atomicAdd(&cnt_sm[c], 1);
                list_sm[c * 128 + pos] = (unsigned char)wp_tid;
            }
            BAR_SYNC(5, 256);                   // lists complete

            // phase 3: warp owns 8 classes, full class row per warp
            #pragma unroll
            for (int cc = 0; cc < 8; cc++) {
                const int c = wp * 8 + cc;
                const int n = cnt_sm[c];
                if (n) {
                    const unsigned char* lst = list_sm + c * 128;
                    float4 a = make_float4(0.f, 0.f, 0.f, 0.f);
                    for (int t = 0; t < n; t++) {
                        const int r = lst[t];
                        const float4 v = *(const float4*)&atf[r * 132 + l * 4];
                        a.x += v.x; a.y += v.y; a.z += v.z; a.w += v.w;
                    }
                    float4* Fp = (float4*)&F_sm[c * 132 + l * 4];
                    float4 f = *Fp;
                    f.x += a.x; f.y += a.y; f.z += a.z; f.w += a.w;
                    *Fp = f;
                }
            }
            if (wp_tid < CC)  cntt_sm[wp_tid] += cnt_sm[wp_tid];
            if (wp_tid < 128) f2acc += (double)f2p[wp_tid];

            BAR_SYNC(6, NTHR);                  // stage full (epilogue done)

            float* gdst = out + 1 + CC * DF + (size_t)tile * 8192;
            if (wp_tid < 4) {
                if (wp_tid < 3) gdst[wp_tid] = stage[wp_tid];
                else            gdst[8191] = stage[127 * 66 + 63];
            }
            for (int qq = wp_tid; qq < 2047; qq += 256) {
                const int j0 = 3 + 4 * qq;
                float4 v;
                v.x = stage[((j0 + 0) >> 6) * 66 + ((j0 + 0) & 63)];
                v.y = stage[((j0 + 1) >> 6) * 66 + ((j0 + 1) & 63)];
                v.z = stage[((j0 + 2) >> 6) * 66 + ((j0 + 2) & 63)];
                v.w = stage[((j0 + 3) >> 6) * 66 + ((j0 + 3) & 63)];
                *(float4*)(gdst + j0) = v;
            }
            BAR_ARR(7, NTHR);                   // stage free
        }
    }

    // ---- flush per-CTA partials ----
    __syncthreads();
    for (int i = tid; i < CC * DF; i += NTHR)
        g_Fpart[bid * CC * DF + i] = F_sm[(i >> 7) * 132 + (i & 127)];
    if (tid < CC) g_cntpart[bid * CC + tid] = cntt_sm[tid];
    {
        double* dred = (double*)(sm + SM_STAGE);
        if (tid >= 256 && tid < 384) dred[tid - 256] = f2acc;
        __syncthreads();
        if (tid == 0) {
            double s0 = 0, s1 = 0, s2 = 0, s3 = 0;
            for (int i = 0; i < 128; i += 4) {
                s0 += dred[i]; s1 += dred[i + 1]; s2 += dred[i + 2]; s3 += dred[i + 3];
            }
            g_f2part[bid] = (float)((s0 + s1) + (s2 + s3));
        }
    }
}

// ============================================================
// finalize 1: one block per class (64 x 128 threads)
// ============================================================
__global__ void __launch_bounds__(128)
k_final1(const float* __restrict__ centers, float* __restrict__ out)
{
    __shared__ float red[128];
    __shared__ int   ired[128];
    __shared__ int   ncls;
    const int c = blockIdx.x, t = threadIdx.x;

    int s = (t < GRID) ? g_cntpart[t * CC + c] : 0;
    if (t + 128 < GRID) s += g_cntpart[(t + 128) * CC + c];
    ired[t] = s;
    __syncthreads();
    for (int off = 64; off; off >>= 1) {
        if (t < off) ired[t] += ired[t + off];
        __syncthreads();
    }
    if (t == 0) ncls = ired[0];
    __syncthreads();
    const int n = ncls;

    const int i = c * DF + t;
    float F0 = 0, F1 = 0, F2 = 0, F3 = 0, F4 = 0, F5 = 0, F6 = 0, F7 = 0;
    #pragma unroll 4
    for (int b = 0; b < GRID; b += 8) {
        F0 += g_Fpart[(b + 0) * CC * DF + i];
        F1 += g_Fpart[(b + 1) * CC * DF + i];
        F2 += g_Fpart[(b + 2) * CC * DF + i];
        F3 += g_Fpart[(b + 3) * CC * DF + i];
        F4 += g_Fpart[(b + 4) * CC * DF + i];
        F5 += g_Fpart[(b + 5) * CC * DF + i];
        F6 += g_Fpart[(b + 6) * CC * DF + i];
        F7 += g_Fpart[(b + 7) * CC * DF + i];
    }
    const float F = ((F0 + F1) + (F2 + F3)) + ((F4 + F5) + (F6 + F7));
    const float cen = centers[i];
    out[1 + i] = (n > 0) ? (cen - F / (float)n) : 0.f;

    red[t] = F * cen;
    __syncthreads();
    for (int off = 64; off; off >>= 1) {
        if (t < off) red[t] += red[t + off];
        __syncthreads();
    }
    if (t == 0) g_s2part[c] = red[0];
    __syncthreads();
    red[t] = cen * cen;
    __syncthreads();
    for (int off = 64; off; off >>= 1) {
        if (t < off) red[t] += red[t + off];
        __syncthreads();
    }
    if (t == 0) g_nc2[c] = (float)n * red[0];
}

// ============================================================
// finalize 2: micro kernel for the loss scalar
// ============================================================
__global__ void __launch_bounds__(128)
k_final2(float* __restrict__ out)
{
    __shared__ float r1[128], r2[128], r3[128];
    const int t = threadIdx.x;
    float a = (t < GRID) ? g_f2part[t] : 0.f;
    if (t + 128 < GRID) a += g_f2part[t + 128];
    r1[t] = a;
    r2[t] = (t < CC) ? g_s2part[t] : 0.f;
    r3[t] = (t < CC) ? g_nc2[t] : 0.f;
    __syncthreads();
    for (int off = 64; off; off >>= 1) {
        if (t < off) { r1[t] += r1[t + off]; r2[t] += r2[t + off]; r3[t] += r3[t + off]; }
        __syncthreads();
    }
    if (t == 0)
        out[0] = (float)(((double)r1[0] - 2.0 * (double)r2[0] + (double)r3[0])
                         / ((double)NTOK * (double)DF));
}

// ============================================================
extern "C" void kernel_launch(void* const* d_in, const int* in_sizes, int n_in,
                              void* d_out, int out_size)
{
    const float* feature = (const float*)d_in[0];
    const int*   label   = (const int*)d_in[1];
    const float* centers = (const float*)d_in[2];
    float*       out     = (float*)d_out;

    cudaFuncSetAttribute(k_main, cudaFuncAttributeMaxDynamicSharedMemorySize, SM_TOTAL);
    k_main<<<GRID, NTHR, SM_TOTAL>>>(feature, label, centers, out);
    k_final1<<<CC, 128>>>(centers, out);
    k_final2<<<1, 128>>>(out);
}